// round 8
// baseline (speedup 1.0000x reference)
#include <cuda_runtime.h>
#include <math.h>
#include <stdint.h>

#define B_ 1024
#define T_ 16
#define D_ 1024
#define H_ 2048
#define O_ 1024

// ---------------- scratch (device globals; no allocation allowed) ----------
__device__ float r8_inp[B_ * T_ * H_];
__device__ float r8_pre[B_ * H_];
__device__ float r8_tmp[B_ * H_];
__device__ float r8_ctx[B_ * H_];
__device__ float r8_rec[B_ * H_];
__device__ float r8_attr[B_ * H_];
__device__ float r8_spk[B_ * H_];

// ---------------- packed fp32 helpers (Blackwell f32x2 pipe) ----------------
__device__ __forceinline__ unsigned long long r8_pk2(float lo, float hi) {
    unsigned long long r;
    asm("mov.b64 %0, {%1, %2};" : "=l"(r) : "f"(lo), "f"(hi));
    return r;
}
__device__ __forceinline__ void r8_up2(unsigned long long v, float& lo, float& hi) {
    asm("mov.b64 {%0, %1}, %2;" : "=f"(lo), "=f"(hi) : "l"(v));
}
__device__ __forceinline__ void r8_fma2(unsigned long long& d,
                                        unsigned long long a, unsigned long long b) {
    asm("fma.rn.f32x2 %0, %1, %2, %3;" : "=l"(d) : "l"(a), "l"(b), "l"(d));
}

// ---------------- fp32 SGEMM via FFMA2: C = alpha*(A1@B1 [+A2@B2]) + bias ---
// Identical math/order to the proven R1 kernel; each acc element accumulates
// k-serially in fp32 RN — outputs bit-identical to R1.
__global__ void __launch_bounds__(256) r8_sgemm_kernel(
    const float* __restrict__ A1, int lda1,
    const float* __restrict__ B1,
    const float* __restrict__ A2, int lda2,
    const float* __restrict__ B2,
    const float* __restrict__ bias1, const float* __restrict__ bias2,
    float* __restrict__ C, int ldc,
    int M, int N, int K, float alpha)
{
    const int BM = 128, BN = 128, BK = 16;
    __shared__ float As[BK][BM];
    __shared__ float Bs[BK][BN];

    const int bm = blockIdx.y * BM;
    const int bn = blockIdx.x * BN;
    const int tid = threadIdx.x;
    const int tr = tid / 16;
    const int tc = tid % 16;

    const int a_r = tid / 4;
    const int a_c = (tid % 4) * 4;
    const int b_r = tid / 32;
    const int b_c = (tid % 32) * 4;

    // acc2[i][j] holds C(row i, cols 2j, 2j+1) packed
    unsigned long long acc2[8][4];
#pragma unroll
    for (int i = 0; i < 8; i++)
#pragma unroll
        for (int j = 0; j < 4; j++) acc2[i][j] = 0ull;

    const int npass = (A2 != nullptr) ? 2 : 1;
    for (int pass = 0; pass < npass; pass++) {
        const float* A  = pass ? A2 : A1;
        const float* Bm = pass ? B2 : B1;
        const int lda   = pass ? lda2 : lda1;

        for (int k0 = 0; k0 < K; k0 += BK) {
#pragma unroll
            for (int i = 0; i < 2; i++) {
                int r = a_r + i * 64;
                float4 v = *(const float4*)(A + (long)(bm + r) * lda + k0 + a_c);
                As[a_c + 0][r] = v.x;
                As[a_c + 1][r] = v.y;
                As[a_c + 2][r] = v.z;
                As[a_c + 3][r] = v.w;
            }
#pragma unroll
            for (int i = 0; i < 2; i++) {
                int r = b_r + i * 8;
                float4 v = *(const float4*)(Bm + (long)(k0 + r) * N + bn + b_c);
                *(float4*)&Bs[r][b_c] = v;
            }
            __syncthreads();

#pragma unroll
            for (int kk = 0; kk < BK; kk++) {
                float4 a0 = *(const float4*)&As[kk][tr * 8];
                float4 a1 = *(const float4*)&As[kk][tr * 8 + 4];
                float4 b0 = *(const float4*)&Bs[kk][tc * 8];
                float4 b1 = *(const float4*)&Bs[kk][tc * 8 + 4];
                float a[8] = {a0.x, a0.y, a0.z, a0.w, a1.x, a1.y, a1.z, a1.w};
                unsigned long long bp[4];
                bp[0] = r8_pk2(b0.x, b0.y);
                bp[1] = r8_pk2(b0.z, b0.w);
                bp[2] = r8_pk2(b1.x, b1.y);
                bp[3] = r8_pk2(b1.z, b1.w);
#pragma unroll
                for (int i = 0; i < 8; i++) {
                    unsigned long long ap = r8_pk2(a[i], a[i]);
#pragma unroll
                    for (int j = 0; j < 4; j++)
                        r8_fma2(acc2[i][j], ap, bp[j]);
                }
            }
            __syncthreads();
        }
    }

    // epilogue (same as R1)
    const int row0 = bm + tr * 8;
    const int col0 = bn + tc * 8;
    float bias[8];
#pragma unroll
    for (int j = 0; j < 8; j++) {
        float v = bias1[col0 + j];
        if (bias2 != nullptr) v += bias2[col0 + j];
        bias[j] = v;
    }
#pragma unroll
    for (int i = 0; i < 8; i++) {
        float c[8];
#pragma unroll
        for (int j = 0; j < 4; j++) r8_up2(acc2[i][j], c[2 * j], c[2 * j + 1]);
        float4 o0, o1;
        o0.x = alpha * c[0] + bias[0];
        o0.y = alpha * c[1] + bias[1];
        o0.z = alpha * c[2] + bias[2];
        o0.w = alpha * c[3] + bias[3];
        o1.x = alpha * c[4] + bias[4];
        o1.y = alpha * c[5] + bias[5];
        o1.z = alpha * c[6] + bias[6];
        o1.w = alpha * c[7] + bias[7];
        *(float4*)(C + (long)(row0 + i) * ldc + col0)     = o0;
        *(float4*)(C + (long)(row0 + i) * ldc + col0 + 4) = o1;
    }
}

// ---------------- elementwise kernels (verbatim R1 numerics) ----------------
__inline__ __device__ float r8_warpsum(float v) {
#pragma unroll
    for (int o = 16; o > 0; o >>= 1) v += __shfl_xor_sync(0xffffffffu, v, o);
    return v;
}

__global__ void __launch_bounds__(256) r8_step1_kernel(
    const float* __restrict__ pre, float* __restrict__ rec,
    float* __restrict__ ctx, float* __restrict__ s,
    const float* __restrict__ gamma, const float* __restrict__ beta)
{
    const int row = blockIdx.x;
    const float* p = pre + (long)row * H_;
    float* r = rec + (long)row * H_;

    float vals[8];
    float sum = 0.f, sumsq = 0.f;
#pragma unroll
    for (int i = 0; i < 8; i++) {
        int h = threadIdx.x + i * 256;
        float u = tanhf(p[h]);
        float nr = 0.9f * r[h] + 0.1f * u;
        r[h] = nr;
        vals[i] = nr;
        sum += nr;
        sumsq += nr * nr;
    }
    float s1 = r8_warpsum(sum), s2 = r8_warpsum(sumsq);
    __shared__ float sh[16];
    int warp = threadIdx.x >> 5, lane = threadIdx.x & 31;
    if (lane == 0) { sh[warp] = s1; sh[8 + warp] = s2; }
    __syncthreads();
    if (threadIdx.x == 0) {
        float a = 0.f, b = 0.f;
#pragma unroll
        for (int i = 0; i < 8; i++) { a += sh[i]; b += sh[8 + i]; }
        sh[0] = a; sh[8] = b;
    }
    __syncthreads();
    const float mean = sh[0] * (1.0f / H_);
    const float var  = sh[8] * (1.0f / H_) - mean * mean;
    const float inv  = rsqrtf(var + 1e-5f);
#pragma unroll
    for (int i = 0; i < 8; i++) {
        int h = threadIdx.x + i * 256;
        float c = (vals[i] - mean) * inv * gamma[h] + beta[h];
        ctx[(long)row * H_ + h] = c;
        s[(long)row * H_ + h]   = c + vals[i];
    }
}

__global__ void __launch_bounds__(256) r8_step2_kernel(
    const float* __restrict__ pre, const float* __restrict__ ctx,
    const float* __restrict__ rec, float* __restrict__ gated)
{
    long i = (long)blockIdx.x * blockDim.x + threadIdx.x;
    const float4 p = ((const float4*)pre)[i];
    const float4 c = ((const float4*)ctx)[i];
    const float4 r = ((const float4*)rec)[i];
    float4 o;
    float g;
    g = 1.0f / (1.0f + expf(-p.x)); o.x = g * c.x + (1.0f - g) * r.x;
    g = 1.0f / (1.0f + expf(-p.y)); o.y = g * c.y + (1.0f - g) * r.y;
    g = 1.0f / (1.0f + expf(-p.z)); o.z = g * c.z + (1.0f - g) * r.z;
    g = 1.0f / (1.0f + expf(-p.w)); o.w = g * c.w + (1.0f - g) * r.w;
    ((float4*)gated)[i] = o;
}

__global__ void __launch_bounds__(256) r8_step3_kernel(
    const float* __restrict__ cur, float* __restrict__ attr,
    float* __restrict__ spk)
{
    long i = (long)blockIdx.x * blockDim.x + threadIdx.x;
    const float4 c = ((const float4*)cur)[i];
    float4 a = ((float4*)attr)[i];
    float4 sp = ((float4*)spk)[i];
    float v, s;
    v = a.x + (c.x - a.x) * 0.5f; s = (v > 1.0f) ? 1.0f : 0.0f; a.x = v - s; sp.x += s;
    v = a.y + (c.y - a.y) * 0.5f; s = (v > 1.0f) ? 1.0f : 0.0f; a.y = v - s; sp.y += s;
    v = a.z + (c.z - a.z) * 0.5f; s = (v > 1.0f) ? 1.0f : 0.0f; a.z = v - s; sp.z += s;
    v = a.w + (c.w - a.w) * 0.5f; s = (v > 1.0f) ? 1.0f : 0.0f; a.w = v - s; sp.w += s;
    ((float4*)attr)[i] = a;
    ((float4*)spk)[i]  = sp;
}

__global__ void __launch_bounds__(256) r8_init_kernel(
    float* __restrict__ rec, float* __restrict__ attr, float* __restrict__ spk)
{
    long i = (long)blockIdx.x * blockDim.x + threadIdx.x;
    float4 z = make_float4(0.f, 0.f, 0.f, 0.f);
    ((float4*)rec)[i]  = z;
    ((float4*)attr)[i] = z;
    ((float4*)spk)[i]  = z;
}

__global__ void __launch_bounds__(256) r8_tail_kernel(
    const float* __restrict__ rec, const float* __restrict__ attr,
    float* __restrict__ out)
{
    long i = (long)blockIdx.x * blockDim.x + threadIdx.x;
    ((float4*)out)[i]                   = ((const float4*)rec)[i];
    ((float4*)(out + (long)B_ * H_))[i] = ((const float4*)attr)[i];
}

// ---------------- launch ----------------------------------------------------
extern "C" void kernel_launch(void* const* d_in, const int* in_sizes, int n_in,
                              void* d_out, int out_size)
{
    const float* x       = (const float*)d_in[0];
    const float* Wp      = (const float*)d_in[1];
    const float* bp      = (const float*)d_in[2];
    const float* Wfc     = (const float*)d_in[3];
    const float* bfc     = (const float*)d_in[4];
    const float* gamma   = (const float*)d_in[5];
    const float* beta_ln = (const float*)d_in[6];
    const float* Wg      = (const float*)d_in[7];
    const float* bg      = (const float*)d_in[8];
    const float* Wenc    = (const float*)d_in[9];
    const float* benc    = (const float*)d_in[10];
    const float* Wrec    = (const float*)d_in[11];
    const float* brec    = (const float*)d_in[12];
    const float* Wro     = (const float*)d_in[13];
    const float* bro     = (const float*)d_in[14];
    float* out = (float*)d_out;

    float *inp, *pre, *tmp, *ctx, *rec, *attr, *spk;
    cudaGetSymbolAddress((void**)&inp,  r8_inp);
    cudaGetSymbolAddress((void**)&pre,  r8_pre);
    cudaGetSymbolAddress((void**)&tmp,  r8_tmp);
    cudaGetSymbolAddress((void**)&ctx,  r8_ctx);
    cudaGetSymbolAddress((void**)&rec,  r8_rec);
    cudaGetSymbolAddress((void**)&attr, r8_attr);
    cudaGetSymbolAddress((void**)&spk,  r8_spk);

    const int EW_BLOCKS = (B_ * H_ / 4) / 256;  // 2048

    r8_init_kernel<<<EW_BLOCKS, 256>>>(rec, attr, spk);

    // input projection: [B*T, D] @ [D, H] -> inp [B*T, H]
    {
        dim3 grid(H_ / 128, (B_ * T_) / 128);
        r8_sgemm_kernel<<<grid, 256>>>(x, D_, Wp, nullptr, 0, nullptr,
                                       bp, nullptr, inp, H_,
                                       B_ * T_, H_, D_, 1.0f);
    }

    dim3 gstep(H_ / 128, B_ / 128);  // (16, 8)
    for (int t = 0; t < T_; t++) {
        const float* At = inp + (long)t * H_;  // row stride T*H
        r8_sgemm_kernel<<<gstep, 256>>>(At, T_ * H_, Wfc, nullptr, 0, nullptr,
                                        bfc, nullptr, pre, H_, B_, H_, H_, 1.0f);
        r8_step1_kernel<<<B_, 256>>>(pre, rec, ctx, tmp, gamma, beta_ln);
        r8_sgemm_kernel<<<gstep, 256>>>(tmp, H_, Wg, nullptr, 0, nullptr,
                                        bg, nullptr, pre, H_, B_, H_, H_, 1.0f);
        r8_step2_kernel<<<EW_BLOCKS, 256>>>(pre, ctx, rec, tmp);
        r8_sgemm_kernel<<<gstep, 256>>>(tmp, H_, Wenc, attr, H_, Wrec,
                                        benc, brec, pre, H_, B_, H_, H_, 1.0f);
        r8_step3_kernel<<<EW_BLOCKS, 256>>>(pre, attr, spk);
    }

    // readout: out = (spk/T) @ Wro + bro
    {
        dim3 grid(O_ / 128, B_ / 128);
        r8_sgemm_kernel<<<grid, 256>>>(spk, H_, Wro, nullptr, 0, nullptr,
                                       bro, nullptr, out, O_,
                                       B_, O_, H_, 1.0f / T_);
    }
    r8_tail_kernel<<<EW_BLOCKS, 256>>>(rec, attr, out + (long)B_ * O_);
}